// round 16
// baseline (speedup 1.0000x reference)
#include <cuda_runtime.h>
#include <cuda_fp16.h>
#include <cstdint>

#define TOK   4096
#define HID   2048
#define INTER 5632

// ---- scratch (device globals; no runtime allocation allowed) ----
__device__ __half g_xh[(size_t)TOK * HID];
__device__ __half g_wg[(size_t)INTER * HID];
__device__ __half g_wu[(size_t)INTER * HID];
__device__ __half g_wd[(size_t)HID * INTER];
__device__ __half g_hbuf[(size_t)TOK * INTER];

// ---- sync state ----
__device__ int g_qc, g_q1, g_q2, g_wdd;
__device__ int g_xcnt[32];     // 64 expected each
__device__ int g_wcnt[88];     // 64 expected each (32 wg + 32 wu)
__device__ int g_rowdone[32];  // 88 expected each

#define NCONV 64
#define G1_TASKS 2816          // 32 mb x 88 nb (mb-major)
#define G2_TASKS 512           // 32 mb x 16 nb
#define CT_TOTAL 8384          // 192 x-early + 5632 w + 1856 x-late + 704 wd

__global__ void init_counters() {
  int t = threadIdx.x;
  if (t == 0) { g_qc = 0; g_q1 = 0; g_q2 = 0; g_wdd = 0; }
  if (t < 32) { g_xcnt[t] = 0; g_rowdone[t] = 0; }
  if (t < 88) g_wcnt[t] = 0;
}

// =====================================================================
// helpers
// =====================================================================
__device__ __forceinline__ uint32_t smem_u32(const void* p) {
  uint32_t a;
  asm("{ .reg .u64 t; cvta.to.shared.u64 t, %1; cvt.u32.u64 %0, t; }" : "=r"(a) : "l"(p));
  return a;
}
__device__ __forceinline__ void mma16816(float* c, const uint32_t* a, const uint32_t* b) {
  asm volatile(
      "mma.sync.aligned.m16n8k16.row.col.f32.f16.f16.f32 "
      "{%0,%1,%2,%3}, {%4,%5,%6,%7}, {%8,%9}, {%0,%1,%2,%3};\n"
      : "+f"(c[0]), "+f"(c[1]), "+f"(c[2]), "+f"(c[3])
      : "r"(a[0]), "r"(a[1]), "r"(a[2]), "r"(a[3]), "r"(b[0]), "r"(b[1]));
}
__device__ __forceinline__ void ldsm4(uint32_t* r, uint32_t addr) {
  asm volatile("ldmatrix.sync.aligned.m8n8.x4.shared.b16 {%0,%1,%2,%3}, [%4];"
               : "=r"(r[0]), "=r"(r[1]), "=r"(r[2]), "=r"(r[3]) : "r"(addr));
}
__device__ __forceinline__ void cp16(uint32_t s, const void* g) {
  asm volatile("cp.async.cg.shared.global [%0], [%1], 16;" :: "r"(s), "l"(g));
}
#define CP_COMMIT() asm volatile("cp.async.commit_group;" ::: "memory")
__device__ __forceinline__ int ldvol(const int* p) {
  int v;
  asm volatile("ld.volatile.global.s32 %0, [%1];" : "=r"(v) : "l"(p));
  return v;
}
__device__ __forceinline__ void cvt4(const float* src, __half* dst, size_t idx) {
  float4 v = reinterpret_cast<const float4*>(src)[idx];
  __half2 h0 = __floats2half2_rn(v.x, v.y);
  __half2 h1 = __floats2half2_rn(v.z, v.w);
  reinterpret_cast<__half2*>(dst)[2 * idx]     = h0;
  reinterpret_cast<__half2*>(dst)[2 * idx + 1] = h1;
}

#define SMEM_BYTES (65536 + 16)

// =====================================================================
// Persistent fused kernel with converter/worker CTA specialization.
// =====================================================================
__global__ __launch_bounds__(256, 2)
void fused_mlp(const float* __restrict__ Xf, const float* __restrict__ Wgf,
               const float* __restrict__ Wuf, const float* __restrict__ Wdf,
               const float* __restrict__ gs, const float* __restrict__ us,
               const float* __restrict__ ds, float* __restrict__ Out) {
  extern __shared__ char smem[];
  const uint32_t sb = smem_u32(smem);
  volatile int* bcast = reinterpret_cast<volatile int*>(smem + 65536);
  const int tid = threadIdx.x, lane = tid & 31, warp = tid >> 5;
  const int wm = warp & 3, wn = warp >> 2;
  const int s7 = lane & 7;

  const uint32_t aRow = (uint32_t)((wm * 32 + (lane & 15)) * 128);
  const int hiA = lane >> 4;
  const uint32_t bRow1 = (uint32_t)((wn * 32 + (lane & 7) + ((lane >> 4) & 1) * 8) * 128);
  const uint32_t bRow2 = (uint32_t)((wn * 64 + (lane & 7) + ((lane >> 4) & 1) * 8) * 128);
  const int cB = (lane >> 3) & 1;
  const int g = lane >> 2, t4 = lane & 3;

  // ============ phase C: converter CTAs drain convert queue ============
  if (blockIdx.x < NCONV) {
    for (;;) {
      if (tid == 0) *bcast = atomicAdd(&g_qc, 1);
      __syncthreads();
      const int t = *bcast;
      __syncthreads();
      if (t >= CT_TOTAL) break;
      if (t < 192) {                         // x blocks 0..2
        int xi = t >> 6, s = t & 63;
        size_t base = (size_t)xi * 65536 + (size_t)s * 1024;
#pragma unroll
        for (int i = 0; i < 4; i++) cvt4(Xf, g_xh, base + tid + i * 256);
        __threadfence();
        if (tid == 0) atomicAdd(&g_xcnt[xi], 1);
      } else if (t < 5824) {                 // w blocks 0..87 (wg then wu)
        int j = (t - 192) >> 6, s = (t - 192) & 63;
        const float* src = (s < 32) ? Wgf : Wuf;
        __half* dst = (s < 32) ? g_wg : g_wu;
        size_t base = (size_t)j * 32768 + (size_t)(s & 31) * 1024;
#pragma unroll
        for (int i = 0; i < 4; i++) cvt4(src, dst, base + tid + i * 256);
        __threadfence();
        if (tid == 0) atomicAdd(&g_wcnt[j], 1);
      } else if (t < 7680) {                 // x blocks 3..31
        int xi = 3 + ((t - 5824) >> 6), s = (t - 5824) & 63;
        size_t base = (size_t)xi * 65536 + (size_t)s * 1024;
#pragma unroll
        for (int i = 0; i < 4; i++) cvt4(Xf, g_xh, base + tid + i * 256);
        __threadfence();
        if (tid == 0) atomicAdd(&g_xcnt[xi], 1);
      } else {                               // wd
        int s = t - 7680;
        size_t base = (size_t)s * 4096;
#pragma unroll
        for (int i = 0; i < 16; i++) cvt4(Wdf, g_wd, base + tid + i * 256);
        __threadfence();
        if (tid == 0) atomicAdd(&g_wdd, 1);
      }
    }
  }

  // ================= phase 1: gemm1 tiles (mb-major) =================
  for (;;) {
    if (tid == 0) *bcast = atomicAdd(&g_q1, 1);
    __syncthreads();
    const int task = *bcast;
    __syncthreads();
    if (task >= G1_TASKS) break;
    const int mb = task / 88, nb = task - mb * 88;
    const int mBase = mb * 128, nBase = nb * 64;

    if (tid == 0) {
      while (ldvol(&g_xcnt[mb]) < 64) {}
      while (ldvol(&g_wcnt[nb]) < 64) {}
      __threadfence();
    }
    __syncthreads();

    float ag[2][4][4], au[2][4][4];
#pragma unroll
    for (int i = 0; i < 2; i++)
#pragma unroll
      for (int j = 0; j < 4; j++)
#pragma unroll
        for (int k = 0; k < 4; k++) { ag[i][j][k] = 0.f; au[i][j][k] = 0.f; }

    auto load_stage = [&](int kt, int b) {
      const uint32_t base = sb + (uint32_t)b * 32768u;
      const int k0 = kt * 64;
#pragma unroll
      for (int i = 0; i < 4; i++) {
        int ch = tid + i * 256;
        int row = ch >> 3, c = ch & 7;
        uint32_t sw = (uint32_t)(row * 128 + ((c ^ (row & 7)) << 4));
        cp16(base + sw, g_xh + (size_t)(mBase + row) * HID + k0 + c * 8);
      }
#pragma unroll
      for (int i = 0; i < 2; i++) {
        int ch = tid + i * 256;
        int row = ch >> 3, c = ch & 7;
        uint32_t sw = (uint32_t)(row * 128 + ((c ^ (row & 7)) << 4));
        cp16(base + 16384u + sw, g_wg + (size_t)(nBase + row) * HID + k0 + c * 8);
        cp16(base + 24576u + sw, g_wu + (size_t)(nBase + row) * HID + k0 + c * 8);
      }
      CP_COMMIT();
    };

    const int KT = HID / 64;  // 32
    load_stage(0, 0);
    load_stage(1, 1);

    for (int kt = 0; kt < KT; kt++) {
      const int b = kt & 1;
      if (kt + 1 < KT) asm volatile("cp.async.wait_group 1;" ::: "memory");
      else             asm volatile("cp.async.wait_group 0;" ::: "memory");
      __syncthreads();

      const uint32_t base = sb + (uint32_t)b * 32768u;
      const uint32_t aB = base + aRow;
      const uint32_t gB = base + 16384u + bRow1;
      const uint32_t uB = base + 24576u + bRow1;
#pragma unroll
      for (int kk = 0; kk < 4; kk++) {
        const uint32_t aOff = (uint32_t)((((kk * 2 + hiA) ^ s7)) << 4);
        uint32_t a[2][4];
        ldsm4(a[0], aB + aOff);
        ldsm4(a[1], aB + 2048u + aOff);
        const uint32_t bOff = (uint32_t)((((kk * 2 + cB) ^ s7)) << 4);
        uint32_t bg[2][4], bu[2][4];
#pragma unroll
        for (int np = 0; np < 2; np++) {
          ldsm4(bg[np], gB + (uint32_t)(np * 2048) + bOff);
          ldsm4(bu[np], uB + (uint32_t)(np * 2048) + bOff);
        }
#pragma unroll
        for (int mt = 0; mt < 2; mt++)
#pragma unroll
          for (int np = 0; np < 2; np++) {
            mma16816(ag[mt][np * 2 + 0], a[mt], &bg[np][0]);
            mma16816(ag[mt][np * 2 + 1], a[mt], &bg[np][2]);
            mma16816(au[mt][np * 2 + 0], a[mt], &bu[np][0]);
            mma16816(au[mt][np * 2 + 1], a[mt], &bu[np][2]);
          }
      }
      __syncthreads();
      if (kt + 2 < KT) load_stage(kt + 2, b);
    }

#pragma unroll
    for (int mt = 0; mt < 2; mt++) {
#pragma unroll
      for (int n8 = 0; n8 < 4; n8++) {
        const int col = nBase + wn * 32 + (n8 >> 1) * 16 + (n8 & 1) * 8 + 2 * t4;
        const float gs0 = __ldg(gs + col), gs1 = __ldg(gs + col + 1);
        const float us0 = __ldg(us + col), us1 = __ldg(us + col + 1);
        const float* cg = ag[mt][n8];
        const float* cu = au[mt][n8];
        const int r = mBase + wm * 32 + mt * 16 + g;

        float g00 = cg[0] * gs0, g01 = cg[1] * gs1;
        float g10 = cg[2] * gs0, g11 = cg[3] * gs1;
        float u00 = cu[0] * us0, u01 = cu[1] * us1;
        float u10 = cu[2] * us0, u11 = cu[3] * us1;

        float h00 = g00 / (1.f + expf(-g00)) * u00;
        float h01 = g01 / (1.f + expf(-g01)) * u01;
        float h10 = g10 / (1.f + expf(-g10)) * u10;
        float h11 = g11 / (1.f + expf(-g11)) * u11;

        *reinterpret_cast<__half2*>(g_hbuf + (size_t)r * INTER + col) =
            __floats2half2_rn(h00, h01);
        *reinterpret_cast<__half2*>(g_hbuf + (size_t)(r + 8) * INTER + col) =
            __floats2half2_rn(h10, h11);
      }
    }
    __syncthreads();
    if (tid == 0) {
      __threadfence();
      atomicAdd(&g_rowdone[mb], 1);
    }
  }

  // ================= phase 2: gemm2 tiles =================
  for (;;) {
    if (tid == 0) *bcast = atomicAdd(&g_q2, 1);
    __syncthreads();
    const int task = *bcast;
    __syncthreads();
    if (task >= G2_TASKS) break;
    const int mb = task / 16, nb = task - mb * 16;
    const int mBase = mb * 128, nBase = nb * 128;

    if (tid == 0) {
      while (ldvol(&g_wdd) < 704) {}
      while (ldvol(&g_rowdone[mb]) < 88) {}
      __threadfence();
    }
    __syncthreads();

    float acc[2][8][4];
#pragma unroll
    for (int i = 0; i < 2; i++)
#pragma unroll
      for (int j = 0; j < 8; j++)
#pragma unroll
        for (int k = 0; k < 4; k++) acc[i][j][k] = 0.f;

    auto load_stage2 = [&](int kt, int b) {
      const uint32_t base = sb + (uint32_t)b * 32768u;
      const int k0 = kt * 64;
#pragma unroll
      for (int i = 0; i < 4; i++) {
        int ch = tid + i * 256;
        int row = ch >> 3, c = ch & 7;
        uint32_t sw = (uint32_t)(row * 128 + ((c ^ (row & 7)) << 4));
        cp16(base + sw,          g_hbuf + (size_t)(mBase + row) * INTER + k0 + c * 8);
        cp16(base + 16384u + sw, g_wd   + (size_t)(nBase + row) * INTER + k0 + c * 8);
      }
      CP_COMMIT();
    };

    const int KT = INTER / 64;  // 88
    load_stage2(0, 0);
    load_stage2(1, 1);

    for (int kt = 0; kt < KT; kt++) {
      const int b = kt & 1;
      if (kt + 1 < KT) asm volatile("cp.async.wait_group 1;" ::: "memory");
      else             asm volatile("cp.async.wait_group 0;" ::: "memory");
      __syncthreads();

      const uint32_t base = sb + (uint32_t)b * 32768u;
      const uint32_t aB = base + aRow;
      const uint32_t bB = base + 16384u + bRow2;
#pragma unroll
      for (int kk = 0; kk < 4; kk++) {
        const uint32_t aOff = (uint32_t)((((kk * 2 + hiA) ^ s7)) << 4);
        uint32_t a[2][4];
        ldsm4(a[0], aB + aOff);
        ldsm4(a[1], aB + 2048u + aOff);
        const uint32_t bOff = (uint32_t)((((kk * 2 + cB) ^ s7)) << 4);
        uint32_t bf[4][4];
#pragma unroll
        for (int np = 0; np < 4; np++)
          ldsm4(bf[np], bB + (uint32_t)(np * 2048) + bOff);
#pragma unroll
        for (int mt = 0; mt < 2; mt++)
#pragma unroll
          for (int np = 0; np < 4; np++) {
            mma16816(acc[mt][np * 2 + 0], a[mt], &bf[np][0]);
            mma16816(acc[mt][np * 2 + 1], a[mt], &bf[np][2]);
          }
      }
      __syncthreads();
      if (kt + 2 < KT) load_stage2(kt + 2, b);
    }

#pragma unroll
    for (int mt = 0; mt < 2; mt++) {
#pragma unroll
      for (int n8 = 0; n8 < 8; n8++) {
        const int col = nBase + wn * 64 + (n8 >> 1) * 16 + (n8 & 1) * 8 + 2 * t4;
        const float d0 = __ldg(ds + col), d1 = __ldg(ds + col + 1);
        const float* cc = acc[mt][n8];
        const int r = mBase + wm * 32 + mt * 16 + g;
        *reinterpret_cast<float2*>(Out + (size_t)r * HID + col) =
            make_float2(cc[0] * d0, cc[1] * d1);
        *reinterpret_cast<float2*>(Out + (size_t)(r + 8) * HID + col) =
            make_float2(cc[2] * d0, cc[3] * d1);
      }
    }
  }
}

// =====================================================================
extern "C" void kernel_launch(void* const* d_in, const int* in_sizes, int n_in,
                              void* d_out, int out_size) {
  const float* x      = (const float*)d_in[0];
  const float* gate_w = (const float*)d_in[1];
  const float* up_w   = (const float*)d_in[2];
  const float* down_w = (const float*)d_in[3];
  const float* gate_s = (const float*)d_in[4];
  const float* up_s   = (const float*)d_in[5];
  const float* down_s = (const float*)d_in[6];
  float* out = (float*)d_out;

  cudaFuncSetAttribute(fused_mlp, cudaFuncAttributeMaxDynamicSharedMemorySize, SMEM_BYTES);

  init_counters<<<1, 96>>>();
  fused_mlp<<<304, 256, SMEM_BYTES>>>(x, gate_w, up_w, down_w,
                                      gate_s, up_s, down_s, out);
}